// round 15
// baseline (speedup 1.0000x reference)
#include <cuda_runtime.h>
#include <cuda_fp16.h>
#include <mma.h>
#include <cstdint>
#include <cstddef>

using namespace nvcuda;

#define Bsz 16
#define Cc  512
#define HWn 3136
#define Kw  128

typedef wmma::fragment<wmma::matrix_a, 16, 16, 16, __half, wmma::row_major> HFragA;
typedef wmma::fragment<wmma::matrix_b, 16, 16, 16, __half, wmma::row_major> HFragB;
typedef wmma::fragment<wmma::matrix_b, 16, 16, 16, __half, wmma::col_major> HFragBc;
typedef wmma::fragment<wmma::accumulator, 16, 16, 16, float> HFragC;

// ---------------- scratch ----------------
__device__ __half g_phi[Bsz * Kw * HWn];    // relu(phi_w@x+b), [b][k][n], half
__device__ __half g_Ph[Bsz * Kw * HWn];     // P = phi*inv, [b][k][n], half
__device__ __half g_Pth[Bsz * HWn * Kw];    // P transposed, [b][n][k], half
__device__ __half g_xh[Bsz * Cc * HWn];     // x as half, flat raw cast
__device__ __half g_phiwh[Kw * Cc];         // phi_w half
__device__ __half g_zwh[Cc * Cc];           // zeta_w half, [co][ci]
__device__ __half g_wTh[Bsz * Cc * Kw];     // wT[b][co][k] = -rou[k]*(t@zetaT)[k][co]
__device__ float g_inv[Bsz * HWn];
__device__ float g_s[Bsz * Kw];
__device__ float g_rou[Bsz * Kw];
__device__ float g_pooled[Bsz * Cc];
__device__ float g_t[Bsz * Kw * Cc];
__device__ float g_t2[Bsz * Kw * Cc];
__device__ float g_zetaT[Cc * Cc];          // zeta_w transposed (fp32, for w_gemm)

// ---------------- cp.async helpers ----------------
__device__ __forceinline__ uint32_t s2u(const void* p) {
    return (uint32_t)__cvta_generic_to_shared(p);
}
__device__ __forceinline__ void cpa16(uint32_t dst, const void* src) {
    asm volatile("cp.async.cg.shared.global [%0], [%1], 16;\n" :: "r"(dst), "l"(src));
}
__device__ __forceinline__ void cpa16z(uint32_t dst, const void* src, bool valid) {
    int sz = valid ? 16 : 0;
    asm volatile("cp.async.cg.shared.global [%0], [%1], 16, %2;\n" :: "r"(dst), "l"(src), "r"(sz));
}
#define CP_COMMIT() asm volatile("cp.async.commit_group;\n")
#define CP_WAIT(n)  asm volatile("cp.async.wait_group %0;\n" :: "n"(n))

// ---------------- 1) pooled ----------------
__global__ void pool_kernel(const float* __restrict__ y) {
    int bc = blockIdx.x;
    const float4* p4 = (const float4*)(y + (size_t)bc * HWn);
    float sum = 0.f;
    for (int i = threadIdx.x; i < HWn / 4; i += 256) {
        float4 v = p4[i];
        sum += v.x + v.y + v.z + v.w;
    }
    __shared__ float red[8];
    for (int o = 16; o; o >>= 1) sum += __shfl_down_sync(0xffffffffu, sum, o);
    if ((threadIdx.x & 31) == 0) red[threadIdx.x >> 5] = sum;
    __syncthreads();
    if (threadIdx.x < 8) {
        float v = red[threadIdx.x];
        for (int o = 4; o; o >>= 1) v += __shfl_down_sync(0xffu, v, o);
        if (threadIdx.x == 0) g_pooled[bc] = v / (float)HWn;
    }
}

// ---------------- 2) rou ----------------
__global__ void rou_kernel(const float* __restrict__ rou_w, const float* __restrict__ rou_b) {
    int b = blockIdx.x;
    __shared__ float sp[Cc];
    for (int i = threadIdx.x; i < Cc; i += 128) sp[i] = g_pooled[b * Cc + i];
    __syncthreads();
    int k = threadIdx.x;
    const float* wr = rou_w + k * Cc;
    float acc = rou_b[k];
#pragma unroll 8
    for (int c = 0; c < Cc; c++) acc += sp[c] * wr[c];
    g_rou[b * Kw + k] = 1.f / (1.f + __expf(-acc));
}

// ---------------- 3) zetaT (fp32, for w_gemm) ----------------
__global__ void transpose_kernel(const float* __restrict__ zw) {
    __shared__ float tile[32][33];
    int cx = blockIdx.x * 32 + threadIdx.x;
    int cy = blockIdx.y * 32;
    for (int j = 0; j < 32; j += 8)
        tile[threadIdx.y + j][threadIdx.x] = zw[(cy + threadIdx.y + j) * Cc + cx];
    __syncthreads();
    int ox = blockIdx.y * 32 + threadIdx.x;
    int oy = blockIdx.x * 32;
    for (int j = 0; j < 32; j += 8)
        g_zetaT[(oy + threadIdx.y + j) * Cc + ox] = tile[threadIdx.x][threadIdx.y + j];
}

// ---------------- 3b) cast weights to half ----------------
__global__ void castw_kernel(const float* __restrict__ phi_w, const float* __restrict__ zeta_w) {
    int i = blockIdx.x * 256 + threadIdx.x;
    if (i < Kw * Cc) g_phiwh[i] = __float2half(phi_w[i]);
    if (i < Cc * Cc) g_zwh[i] = __float2half(zeta_w[i]);
}

// ---------------- 3c) x -> half, FLAT raw cast ----------------
__global__ void xh_kernel(const float* __restrict__ x) {
    size_t i = ((size_t)blockIdx.x * 256 + threadIdx.x) * 8;
    const size_t total = (size_t)Bsz * Cc * HWn;
    if (i < total) {
        float4 a = *(const float4*)&x[i];
        float4 b = *(const float4*)&x[i + 4];
        __half h[8];
        h[0] = __float2half(a.x); h[1] = __float2half(a.y);
        h[2] = __float2half(a.z); h[3] = __float2half(a.w);
        h[4] = __float2half(b.x); h[5] = __float2half(b.y);
        h[6] = __float2half(b.z); h[7] = __float2half(b.w);
        *(uint4*)&g_xh[i] = *(uint4*)h;
    }
}

// ---------------- 4) phi GEMM: FP16 wmma, K-chunk 64, 3-stage, 1 sync/iter ----------------
// M=128(k) x N=128(n), K=512. grid (25, B).
#define PH_AS 72
#define PH_BS 136
#define PH_AF (128 * PH_AS)                 // 9216 halves
#define PH_BF (64 * PH_BS)                  // 8704 halves
#define PH_STG (PH_AF + PH_BF)              // 17920 halves = 35840 B
__global__ __launch_bounds__(256, 2) void phi_gemm_h(const float* __restrict__ phi_b) {
    extern __shared__ char smraw[];
    __half* smh = (__half*)smraw;
    float* Cs = (float*)smraw;              // [128][132] overlay
    int b = blockIdx.y, n0 = blockIdx.x * 128;
    const __half* xhb = g_xh + (size_t)b * Cc * HWn;   // [c][n]
    int tid = threadIdx.x, wid = tid >> 5;
    int wm = wid & 3, wn = wid >> 2;        // warp tile 32(m) x 64(n)

    HFragC acc[2][4];
#pragma unroll
    for (int i = 0; i < 2; i++)
#pragma unroll
        for (int j = 0; j < 4; j++) wmma::fill_fragment(acc[i][j], 0.f);

    auto prefetch = [&](int ch) {
        __half* A = smh + (ch % 3) * PH_STG;
        __half* B = A + PH_AF;
        int k0 = ch * 64;
#pragma unroll
        for (int j = 0; j < 4; j++) {       // A: phi_w 128x64 half
            int f = tid + j * 256;
            int m = f >> 3, q = f & 7;
            cpa16(s2u(&A[m * PH_AS + q * 8]), &g_phiwh[m * Cc + k0 + q * 8]);
        }
#pragma unroll
        for (int j = 0; j < 4; j++) {       // B: x 64x128 half
            int f = tid + j * 256;
            int kk = f >> 4, n8 = f & 15;
            int n = n0 + n8 * 8;
            cpa16z(s2u(&B[kk * PH_BS + n8 * 8]), &xhb[(size_t)(k0 + kk) * HWn + n], n < HWn);
        }
        CP_COMMIT();
    };

    prefetch(0); prefetch(1);
    const int NCH = Cc / 64;                // 8
    for (int ch = 0; ch < NCH; ch++) {
        if (ch < NCH - 1) CP_WAIT(1); else CP_WAIT(0);
        __syncthreads();                    // chunk ch visible; stage (ch+2)%3 free
        if (ch + 2 < NCH) prefetch(ch + 2);
        __half* A = smh + (ch % 3) * PH_STG;
        __half* B = A + PH_AF;
#pragma unroll
        for (int s = 0; s < 4; s++) {       // 4 x k16 steps
            HFragA a[2]; HFragB bf[4];
#pragma unroll
            for (int i = 0; i < 2; i++)
                wmma::load_matrix_sync(a[i], &A[(wm * 32 + i * 16) * PH_AS + s * 16], PH_AS);
#pragma unroll
            for (int j = 0; j < 4; j++)
                wmma::load_matrix_sync(bf[j], &B[(s * 16) * PH_BS + wn * 64 + j * 16], PH_BS);
#pragma unroll
            for (int i = 0; i < 2; i++)
#pragma unroll
                for (int j = 0; j < 4; j++) wmma::mma_sync(acc[i][j], a[i], bf[j], acc[i][j]);
        }
    }
    __syncthreads();
#pragma unroll
    for (int i = 0; i < 2; i++)
#pragma unroll
        for (int j = 0; j < 4; j++)
            wmma::store_matrix_sync(&Cs[(wm * 32 + i * 16) * 132 + wn * 64 + j * 16],
                                    acc[i][j], 132, wmma::mem_row_major);
    __syncthreads();
    __half* outp = g_phi + (size_t)b * Kw * HWn;
#pragma unroll
    for (int j = 0; j < 8; j++) {
        int f = tid + j * 256;
        int m = f >> 4, c8 = f & 15;
        int n = n0 + c8 * 8;
        if (n < HWn) {
            float bias = phi_b[m];
            const float* s = &Cs[m * 132 + c8 * 8];
            __half h[8];
#pragma unroll
            for (int q = 0; q < 8; q++) h[q] = __float2half(fmaxf(s[q] + bias, 0.f));
            *(uint4*)&outp[(size_t)m * HWn + n] = *(uint4*)h;
        }
    }
}

// ---------------- 5) s[b,k] = sum_n phi ----------------
__global__ void s_kernel() {
    int bk = blockIdx.x;
    const __half2* p2 = (const __half2*)(g_phi + (size_t)bk * HWn);
    float sum = 0.f;
    for (int i = threadIdx.x; i < HWn / 2; i += 256) {
        float2 v = __half22float2(p2[i]);
        sum += v.x + v.y;
    }
    __shared__ float red[8];
    for (int o = 16; o; o >>= 1) sum += __shfl_down_sync(0xffffffffu, sum, o);
    if ((threadIdx.x & 31) == 0) red[threadIdx.x >> 5] = sum;
    __syncthreads();
    if (threadIdx.x < 8) {
        float v = red[threadIdx.x];
        for (int o = 4; o; o >>= 1) v += __shfl_down_sync(0xffu, v, o);
        if (threadIdx.x == 0) g_s[bk] = v;
    }
}

// ---------------- 6) inv ----------------
__global__ void d_kernel() {
    int b = blockIdx.y;
    __shared__ float coef[Kw];
    if (threadIdx.x < Kw) coef[threadIdx.x] = g_rou[b * Kw + threadIdx.x] * g_s[b * Kw + threadIdx.x];
    __syncthreads();
    int n = blockIdx.x * 256 + threadIdx.x;
    if (n < HWn) {
        const __half* p = g_phi + (size_t)b * Kw * HWn + n;
        float acc = 0.f;
#pragma unroll 8
        for (int k = 0; k < Kw; k++) acc += __half2float(p[(size_t)k * HWn]) * coef[k];
        g_inv[b * HWn + n] = rsqrtf(acc + 1e-8f);
    }
}

// ---------------- 6b) P in two half layouts ----------------
__global__ void ps_kernel() {
    int n0 = blockIdx.x * 32, k0 = blockIdx.y * 32, b = blockIdx.z;
    const __half* phib = g_phi + (size_t)b * Kw * HWn;
    __half* phb = g_Ph + (size_t)b * Kw * HWn;
    __shared__ float tile[32][33];
    float inv = g_inv[b * HWn + n0 + threadIdx.x];
#pragma unroll
    for (int j = 0; j < 32; j += 8) {
        int k = k0 + threadIdx.y + j;
        float v = __half2float(phib[(size_t)k * HWn + n0 + threadIdx.x]) * inv;
        phb[(size_t)k * HWn + n0 + threadIdx.x] = __float2half(v);
        tile[threadIdx.y + j][threadIdx.x] = v;
    }
    __syncthreads();
    __half* ptb = g_Pth + (size_t)b * HWn * Kw;
#pragma unroll
    for (int j = 0; j < 32; j += 8) {
        int n = n0 + threadIdx.y + j;
        ptb[(size_t)n * Kw + k0 + threadIdx.x] = __float2half(tile[threadIdx.x][threadIdx.y + j]);
    }
}

// ---------------- 7) t GEMM: FP16 wmma, K-chunk 64, 3-stage, split-K=2 (25/24) ----------------
#define T_AS 72
#define T_BS 72
#define T_AF (128 * T_AS)                   // 9216 halves
#define T_BF (64 * T_BS)                    // 4608 halves
#define T_STG (T_AF + T_BF)                 // 13824 halves = 27648 B
__global__ __launch_bounds__(256, 2) void t_gemm_h() {
    extern __shared__ char smraw[];
    __half* smh = (__half*)smraw;
    int c0 = blockIdx.x * 64, split = blockIdx.y, b = blockIdx.z;
    const __half* phb = g_Ph + (size_t)b * Kw * HWn;
    const __half* xfh = g_xh + (size_t)b * Cc * HWn;   // flat: X2[n][c]
    int tid = threadIdx.x, wid = tid >> 5;
    int wm = wid & 3, wn = wid >> 2;        // warp tile 32(k) x 32(c)
    int cstart = split ? 25 : 0;
    const int NCH = split ? 24 : 25;

    HFragC acc[2][2];
#pragma unroll
    for (int i = 0; i < 2; i++)
#pragma unroll
        for (int j = 0; j < 2; j++) wmma::fill_fragment(acc[i][j], 0.f);

    auto prefetch = [&](int ch) {
        __half* A = smh + (ch % 3) * T_STG;
        __half* B = A + T_AF;
        int nb = (cstart + ch) * 64;
#pragma unroll
        for (int j = 0; j < 4; j++) {       // A: P 128x64
            int f = tid + j * 256;
            int m = f >> 3, q = f & 7;
            cpa16(s2u(&A[m * T_AS + q * 8]), &phb[(size_t)m * HWn + nb + q * 8]);
        }
#pragma unroll
        for (int j = 0; j < 2; j++) {       // B: X2h 64x64
            int f = tid + j * 256;
            int kk = f >> 3, q = f & 7;
            cpa16(s2u(&B[kk * T_BS + q * 8]), &xfh[(size_t)(nb + kk) * Cc + c0 + q * 8]);
        }
        CP_COMMIT();
    };

    prefetch(0); prefetch(1);
    for (int ch = 0; ch < NCH; ch++) {
        if (ch < NCH - 1) CP_WAIT(1); else CP_WAIT(0);
        __syncthreads();
        if (ch + 2 < NCH) prefetch(ch + 2);
        __half* A = smh + (ch % 3) * T_STG;
        __half* B = A + T_AF;
#pragma unroll
        for (int s = 0; s < 4; s++) {
            HFragA a[2]; HFragB bf[2];
#pragma unroll
            for (int i = 0; i < 2; i++)
                wmma::load_matrix_sync(a[i], &A[(wm * 32 + i * 16) * T_AS + s * 16], T_AS);
#pragma unroll
            for (int j = 0; j < 2; j++)
                wmma::load_matrix_sync(bf[j], &B[(s * 16) * T_BS + wn * 32 + j * 16], T_BS);
#pragma unroll
            for (int i = 0; i < 2; i++)
#pragma unroll
                for (int j = 0; j < 2; j++) wmma::mma_sync(acc[i][j], a[i], bf[j], acc[i][j]);
        }
    }
    float* tb = (split ? g_t2 : g_t) + (size_t)b * Kw * Cc;
#pragma unroll
    for (int i = 0; i < 2; i++)
#pragma unroll
        for (int j = 0; j < 2; j++)
            wmma::store_matrix_sync(&tb[(size_t)(wm * 32 + i * 16) * Cc + c0 + wn * 32 + j * 16],
                                    acc[i][j], Cc, wmma::mem_row_major);
}

// ---------------- 8) w GEMM (SIMT fp32): wTh[co][k] = -rou[k]*((t0+t1)@zetaT)[k][co] ----------------
__global__ __launch_bounds__(256) void w_gemm_kernel() {
    int b = blockIdx.z, m0 = blockIdx.y * 64, c0 = blockIdx.x * 64;
    const float* tb = g_t + (size_t)b * Kw * Cc;
    const float* tb2 = g_t2 + (size_t)b * Kw * Cc;
    __shared__ float As[16][64];
    __shared__ float Bs[16][64];
    float acc[4][4] = {};
    int tid = threadIdx.x, tx = tid & 15, ty = tid >> 4;

    for (int kk0 = 0; kk0 < Cc; kk0 += 16) {
        __syncthreads();
        {
            int m = tid >> 2, q = tid & 3;
            size_t off = (size_t)(m0 + m) * Cc + kk0 + q * 4;
            float4 v = *(const float4*)&tb[off];
            float4 v2 = *(const float4*)&tb2[off];
            As[q * 4 + 0][m] = v.x + v2.x; As[q * 4 + 1][m] = v.y + v2.y;
            As[q * 4 + 2][m] = v.z + v2.z; As[q * 4 + 3][m] = v.w + v2.w;
        }
        {
            int kk = tid >> 4, c4 = tid & 15;
            float4 v = *(const float4*)&g_zetaT[(size_t)(kk0 + kk) * Cc + c0 + c4 * 4];
            *(float4*)&Bs[kk][c4 * 4] = v;
        }
        __syncthreads();
#pragma unroll
        for (int kk = 0; kk < 16; kk++) {
            float4 a = *(float4*)&As[kk][ty * 4];
            float4 bb = *(float4*)&Bs[kk][tx * 4];
            float av[4] = {a.x, a.y, a.z, a.w};
            float bv[4] = {bb.x, bb.y, bb.z, bb.w};
#pragma unroll
            for (int i = 0; i < 4; i++)
#pragma unroll
                for (int jj = 0; jj < 4; jj++) acc[i][jj] += av[i] * bv[jj];
        }
    }
    __half* wtb = g_wTh + (size_t)b * Cc * Kw;          // [co][k]
#pragma unroll
    for (int i = 0; i < 4; i++) {
        int m = m0 + ty * 4 + i;                        // k index
        float r = -g_rou[b * Kw + m];
#pragma unroll
        for (int jj = 0; jj < 4; jj++) {
            int c = c0 + tx * 4 + jj;                   // co index
            wtb[(size_t)c * Kw + m] = __float2half(r * acc[i][jj]);
        }
    }
}

// ---------------- 9) fused out GEMM: FP16 wmma, block 128x256, warp 64x64 ----------------
// D[n=128, co=256] = [X2|Pt][n,:] @ [zeta_w ; wT][co,:]^T, K=640. grid (25, 2, B).
#define O_AS 72
#define O_AF (128 * O_AS)                   // A: 9216 halves
#define O_BF (256 * O_AS)                   // B: 18432 halves
#define O_STG (O_AF + O_BF)                 // 27648 halves = 55296 B per stage
__global__ __launch_bounds__(256, 1) void out_gemm_h2(
    const float* __restrict__ x, const float* __restrict__ zeta_b, float* __restrict__ out) {
    extern __shared__ char smraw[];
    __half* smh = (__half*)smraw;
    float* Cs = (float*)smraw;              // [128][260] overlay (133120 B)
    int n0 = blockIdx.x * 128, c0 = blockIdx.y * 256, b = blockIdx.z;
    const float* xb = x + (size_t)b * Cc * HWn;
    const __half* xfh = g_xh + (size_t)b * Cc * HWn;   // flat: X2[n][c]
    const __half* pthb = g_Pth + (size_t)b * HWn * Kw;
    const __half* wthb = g_wTh + (size_t)b * Cc * Kw;
    int tid = threadIdx.x, wid = tid >> 5;
    int wm = wid & 1, wn = wid >> 1;        // warp tile 64(n) x 64(co)

    HFragC acc[4][4];
#pragma unroll
    for (int i = 0; i < 4; i++)
#pragma unroll
        for (int j = 0; j < 4; j++) wmma::fill_fragment(acc[i][j], 0.f);

    auto prefetch = [&](int ch) {
        __half* A = smh + (ch % 3) * O_STG;
        __half* B = A + O_AF;
        int k0 = ch * 64;
#pragma unroll
        for (int j = 0; j < 4; j++) {       // A: rows n, 128x64
            int f = tid + j * 256;
            int m = f >> 3, q = f & 7;
            int n = n0 + m;
            bool valid = n < HWn;
            int ns = valid ? n : (HWn - 1);
            const __half* src = (k0 < Cc)
                ? &xfh[(size_t)ns * Cc + k0 + q * 8]
                : &pthb[(size_t)ns * Kw + (k0 - Cc) + q * 8];
            cpa16z(s2u(&A[m * O_AS + q * 8]), src, valid);
        }
#pragma unroll
        for (int j = 0; j < 8; j++) {       // B: rows co, 256x64 (K-major)
            int f = tid + j * 256;
            int m = f >> 3, q = f & 7;
            int co = c0 + m;
            const __half* src = (k0 < Cc)
                ? &g_zwh[(size_t)co * Cc + k0 + q * 8]
                : &wthb[(size_t)co * Kw + (k0 - Cc) + q * 8];
            cpa16(s2u(&B[m * O_AS + q * 8]), src);
        }
        CP_COMMIT();
    };

    prefetch(0); prefetch(1);
    const int NCH = 10;                     // 640 / 64; k0=512 boundary chunk-aligned
    for (int ch = 0; ch < NCH; ch++) {
        if (ch < NCH - 1) CP_WAIT(1); else CP_WAIT(0);
        __syncthreads();                    // chunk ch visible; stage (ch+2)%3 free
        if (ch + 2 < NCH) prefetch(ch + 2);
        __half* A = smh + (ch % 3) * O_STG;
        __half* B = A + O_AF;
#pragma unroll
        for (int s = 0; s < 4; s++) {
            HFragA a[4]; HFragBc bf[4];
#pragma unroll
            for (int i = 0; i < 4; i++)
                wmma::load_matrix_sync(a[i], &A[(wm * 64 + i * 16) * O_AS + s * 16], O_AS);
#pragma unroll
            for (int j = 0; j < 4; j++)
                wmma::load_matrix_sync(bf[j], &B[(wn * 64 + j * 16) * O_AS + s * 16], O_AS);
#pragma unroll
            for (int i = 0; i < 4; i++)
#pragma unroll
                for (int j = 0; j < 4; j++) wmma::mma_sync(acc[i][j], a[i], bf[j], acc[i][j]);
        }
    }
    __syncthreads();
#pragma unroll
    for (int i = 0; i < 4; i++)
#pragma unroll
        for (int j = 0; j < 4; j++)
            wmma::store_matrix_sync(&Cs[(wm * 64 + i * 16) * 260 + wn * 64 + j * 16],
                                    acc[i][j], 260, wmma::mem_row_major);
    __syncthreads();
    float* outb = out + (size_t)b * Cc * HWn;
#pragma unroll
    for (int j = 0; j < 32; j++) {          // 128 x 64 float4
        int f = tid + j * 256;
        int m = f >> 6, c4 = f & 63;
        int n = n0 + m;
        if (n < HWn) {
            int c = c0 + c4 * 4;
            size_t idx = (size_t)n * Cc + c;
            float4 xv = *(const float4*)&xb[idx];
            float4 bz = *(const float4*)&zeta_b[c];
            const float* s = &Cs[m * 260 + c4 * 4];
            float4 v;
            v.x = xv.x + fmaxf(s[0] + bz.x, 0.f);
            v.y = xv.y + fmaxf(s[1] + bz.y, 0.f);
            v.z = xv.z + fmaxf(s[2] + bz.z, 0.f);
            v.w = xv.w + fmaxf(s[3] + bz.w, 0.f);
            *(float4*)&outb[idx] = v;
        }
    }
}

// ---------------- launch ----------------
extern "C" void kernel_launch(void* const* d_in, const int* in_sizes, int n_in,
                              void* d_out, int out_size) {
    const float* x      = (const float*)d_in[0];
    const float* y      = (const float*)d_in[1];
    const float* phi_w  = (const float*)d_in[2];
    const float* phi_b  = (const float*)d_in[3];
    const float* rou_w  = (const float*)d_in[4];
    const float* rou_b  = (const float*)d_in[5];
    const float* zeta_w = (const float*)d_in[6];
    const float* zeta_b = (const float*)d_in[7];
    float* out = (float*)d_out;

    const int PHI_SMEM = 3 * PH_STG * 2;    // 107520 B
    const int T_SMEM   = 3 * T_STG * 2;     // 82944 B
    const int O_SMEM   = 3 * O_STG * 2;     // 165888 B (>= Cs 133120)
    cudaFuncSetAttribute(phi_gemm_h,  cudaFuncAttributeMaxDynamicSharedMemorySize, PHI_SMEM);
    cudaFuncSetAttribute(t_gemm_h,    cudaFuncAttributeMaxDynamicSharedMemorySize, T_SMEM);
    cudaFuncSetAttribute(out_gemm_h2, cudaFuncAttributeMaxDynamicSharedMemorySize, O_SMEM);

    pool_kernel<<<Bsz * Cc, 256>>>(y);
    rou_kernel<<<Bsz, 128>>>(rou_w, rou_b);
    transpose_kernel<<<dim3(Cc / 32, Cc / 32), dim3(32, 8)>>>(zeta_w);
    castw_kernel<<<(Cc * Cc + 255) / 256, 256>>>(phi_w, zeta_w);
    xh_kernel<<<(int)(((size_t)Bsz * Cc * HWn / 8 + 255) / 256), 256>>>(x);
    phi_gemm_h<<<dim3(25, Bsz), 256, PHI_SMEM>>>(phi_b);
    s_kernel<<<Bsz * Kw, 256>>>();
    d_kernel<<<dim3(13, Bsz), 256>>>();
    ps_kernel<<<dim3(98, 4, Bsz), dim3(32, 8)>>>();
    t_gemm_h<<<dim3(8, 2, Bsz), 256, T_SMEM>>>();
    w_gemm_kernel<<<dim3(Cc / 64, Kw / 64, Bsz), 256>>>();
    out_gemm_h2<<<dim3(25, 2, Bsz), 256, O_SMEM>>>(x, zeta_b, out);
}

// round 16
// speedup vs baseline: 1.2482x; 1.2482x over previous
#include <cuda_runtime.h>
#include <cuda_fp16.h>
#include <mma.h>
#include <cstdint>
#include <cstddef>

using namespace nvcuda;

#define Bsz 16
#define Cc  512
#define HWn 3136
#define Kw  128

typedef wmma::fragment<wmma::matrix_a, 16, 16, 16, __half, wmma::row_major> HFragA;
typedef wmma::fragment<wmma::matrix_b, 16, 16, 16, __half, wmma::row_major> HFragB;
typedef wmma::fragment<wmma::matrix_b, 16, 16, 16, __half, wmma::col_major> HFragBc;
typedef wmma::fragment<wmma::accumulator, 16, 16, 16, float> HFragC;

// ---------------- scratch ----------------
__device__ __half g_phi[Bsz * Kw * HWn];    // relu(phi_w@x+b), [b][k][n], half
__device__ __half g_Ph[Bsz * Kw * HWn];     // P = phi*inv, [b][k][n], half
__device__ __half g_Pth[Bsz * HWn * Kw];    // P transposed, [b][n][k], half
__device__ __half g_xh[Bsz * Cc * HWn];     // x as half, flat raw cast
__device__ __half g_phiwh[Kw * Cc];         // phi_w half
__device__ __half g_zwh[Cc * Cc];           // zeta_w half, [co][ci]
__device__ __half g_wTh[Bsz * Cc * Kw];     // wT[b][co][k] = -rou[k]*(t@zetaT)[k][co]
__device__ float g_spart[Bsz * Kw * 25];    // per-block partial col sums of phi
__device__ float g_s[Bsz * Kw];
__device__ float g_rou[Bsz * Kw];
__device__ float g_pooled[Bsz * Cc];
__device__ float g_t[Bsz * Kw * Cc];
__device__ float g_t2[Bsz * Kw * Cc];
__device__ float g_zetaT[Cc * Cc];          // zeta_w transposed (fp32, for w_gemm)

// ---------------- cp.async helpers ----------------
__device__ __forceinline__ uint32_t s2u(const void* p) {
    return (uint32_t)__cvta_generic_to_shared(p);
}
__device__ __forceinline__ void cpa16(uint32_t dst, const void* src) {
    asm volatile("cp.async.cg.shared.global [%0], [%1], 16;\n" :: "r"(dst), "l"(src));
}
__device__ __forceinline__ void cpa16z(uint32_t dst, const void* src, bool valid) {
    int sz = valid ? 16 : 0;
    asm volatile("cp.async.cg.shared.global [%0], [%1], 16, %2;\n" :: "r"(dst), "l"(src), "r"(sz));
}
#define CP_COMMIT() asm volatile("cp.async.commit_group;\n")
#define CP_WAIT(n)  asm volatile("cp.async.wait_group %0;\n" :: "n"(n))

// ---------------- 1) pooled ----------------
__global__ void pool_kernel(const float* __restrict__ y) {
    int bc = blockIdx.x;
    const float4* p4 = (const float4*)(y + (size_t)bc * HWn);
    float sum = 0.f;
    for (int i = threadIdx.x; i < HWn / 4; i += 256) {
        float4 v = p4[i];
        sum += v.x + v.y + v.z + v.w;
    }
    __shared__ float red[8];
    for (int o = 16; o; o >>= 1) sum += __shfl_down_sync(0xffffffffu, sum, o);
    if ((threadIdx.x & 31) == 0) red[threadIdx.x >> 5] = sum;
    __syncthreads();
    if (threadIdx.x < 8) {
        float v = red[threadIdx.x];
        for (int o = 4; o; o >>= 1) v += __shfl_down_sync(0xffu, v, o);
        if (threadIdx.x == 0) g_pooled[bc] = v / (float)HWn;
    }
}

// ---------------- 2) rou ----------------
__global__ void rou_kernel(const float* __restrict__ rou_w, const float* __restrict__ rou_b) {
    int b = blockIdx.x;
    __shared__ float sp[Cc];
    for (int i = threadIdx.x; i < Cc; i += 128) sp[i] = g_pooled[b * Cc + i];
    __syncthreads();
    int k = threadIdx.x;
    const float* wr = rou_w + k * Cc;
    float acc = rou_b[k];
#pragma unroll 8
    for (int c = 0; c < Cc; c++) acc += sp[c] * wr[c];
    g_rou[b * Kw + k] = 1.f / (1.f + __expf(-acc));
}

// ---------------- 3) zetaT (fp32, for w_gemm) ----------------
__global__ void transpose_kernel(const float* __restrict__ zw) {
    __shared__ float tile[32][33];
    int cx = blockIdx.x * 32 + threadIdx.x;
    int cy = blockIdx.y * 32;
    for (int j = 0; j < 32; j += 8)
        tile[threadIdx.y + j][threadIdx.x] = zw[(cy + threadIdx.y + j) * Cc + cx];
    __syncthreads();
    int ox = blockIdx.y * 32 + threadIdx.x;
    int oy = blockIdx.x * 32;
    for (int j = 0; j < 32; j += 8)
        g_zetaT[(oy + threadIdx.y + j) * Cc + ox] = tile[threadIdx.x][threadIdx.y + j];
}

// ---------------- 3b) cast weights to half ----------------
__global__ void castw_kernel(const float* __restrict__ phi_w, const float* __restrict__ zeta_w) {
    int i = blockIdx.x * 256 + threadIdx.x;
    if (i < Kw * Cc) g_phiwh[i] = __float2half(phi_w[i]);
    if (i < Cc * Cc) g_zwh[i] = __float2half(zeta_w[i]);
}

// ---------------- 3c) x -> half, FLAT raw cast ----------------
__global__ void xh_kernel(const float* __restrict__ x) {
    size_t i = ((size_t)blockIdx.x * 256 + threadIdx.x) * 8;
    const size_t total = (size_t)Bsz * Cc * HWn;
    if (i < total) {
        float4 a = *(const float4*)&x[i];
        float4 b = *(const float4*)&x[i + 4];
        __half h[8];
        h[0] = __float2half(a.x); h[1] = __float2half(a.y);
        h[2] = __float2half(a.z); h[3] = __float2half(a.w);
        h[4] = __float2half(b.x); h[5] = __float2half(b.y);
        h[6] = __float2half(b.z); h[7] = __float2half(b.w);
        *(uint4*)&g_xh[i] = *(uint4*)h;
    }
}

// ---------------- 4) phi GEMM + fused s-partials ----------------
// M=128(k) x N=128(n), K=512. grid (25, B). K-chunk 64, 3-stage, 1 sync/iter.
#define PH_AS 72
#define PH_BS 136
#define PH_AF (128 * PH_AS)                 // 9216 halves
#define PH_BF (64 * PH_BS)                  // 8704 halves
#define PH_STG (PH_AF + PH_BF)              // 17920 halves = 35840 B
__global__ __launch_bounds__(256, 2) void phi_gemm_h(const float* __restrict__ phi_b) {
    extern __shared__ char smraw[];
    __half* smh = (__half*)smraw;
    float* Cs = (float*)smraw;              // [128][132] overlay
    int b = blockIdx.y, n0 = blockIdx.x * 128;
    const __half* xhb = g_xh + (size_t)b * Cc * HWn;   // [c][n]
    int tid = threadIdx.x, wid = tid >> 5;
    int wm = wid & 3, wn = wid >> 2;        // warp tile 32(m) x 64(n)

    HFragC acc[2][4];
#pragma unroll
    for (int i = 0; i < 2; i++)
#pragma unroll
        for (int j = 0; j < 4; j++) wmma::fill_fragment(acc[i][j], 0.f);

    auto prefetch = [&](int ch) {
        __half* A = smh + (ch % 3) * PH_STG;
        __half* B = A + PH_AF;
        int k0 = ch * 64;
#pragma unroll
        for (int j = 0; j < 4; j++) {       // A: phi_w 128x64 half
            int f = tid + j * 256;
            int m = f >> 3, q = f & 7;
            cpa16(s2u(&A[m * PH_AS + q * 8]), &g_phiwh[m * Cc + k0 + q * 8]);
        }
#pragma unroll
        for (int j = 0; j < 4; j++) {       // B: x 64x128 half
            int f = tid + j * 256;
            int kk = f >> 4, n8 = f & 15;
            int n = n0 + n8 * 8;
            cpa16z(s2u(&B[kk * PH_BS + n8 * 8]), &xhb[(size_t)(k0 + kk) * HWn + n], n < HWn);
        }
        CP_COMMIT();
    };

    prefetch(0); prefetch(1);
    const int NCH = Cc / 64;                // 8
    for (int ch = 0; ch < NCH; ch++) {
        if (ch < NCH - 1) CP_WAIT(1); else CP_WAIT(0);
        __syncthreads();                    // chunk ch visible; stage (ch+2)%3 free
        if (ch + 2 < NCH) prefetch(ch + 2);
        __half* A = smh + (ch % 3) * PH_STG;
        __half* B = A + PH_AF;
#pragma unroll
        for (int s = 0; s < 4; s++) {       // 4 x k16 steps
            HFragA a[2]; HFragB bf[4];
#pragma unroll
            for (int i = 0; i < 2; i++)
                wmma::load_matrix_sync(a[i], &A[(wm * 32 + i * 16) * PH_AS + s * 16], PH_AS);
#pragma unroll
            for (int j = 0; j < 4; j++)
                wmma::load_matrix_sync(bf[j], &B[(s * 16) * PH_BS + wn * 64 + j * 16], PH_BS);
#pragma unroll
            for (int i = 0; i < 2; i++)
#pragma unroll
                for (int j = 0; j < 4; j++) wmma::mma_sync(acc[i][j], a[i], bf[j], acc[i][j]);
        }
    }
    __syncthreads();
#pragma unroll
    for (int i = 0; i < 2; i++)
#pragma unroll
        for (int j = 0; j < 4; j++)
            wmma::store_matrix_sync(&Cs[(wm * 32 + i * 16) * 132 + wn * 64 + j * 16],
                                    acc[i][j], 132, wmma::mem_row_major);
    __syncthreads();
    __half* outp = g_phi + (size_t)b * Kw * HWn;
#pragma unroll
    for (int j = 0; j < 8; j++) {
        int f = tid + j * 256;
        int m = f >> 4, c8 = f & 15;
        int n = n0 + c8 * 8;
        if (n < HWn) {
            float bias = phi_b[m];
            const float* s = &Cs[m * 132 + c8 * 8];
            __half h[8];
#pragma unroll
            for (int q = 0; q < 8; q++) h[q] = __float2half(fmaxf(s[q] + bias, 0.f));
            *(uint4*)&outp[(size_t)m * HWn + n] = *(uint4*)h;
        }
    }
    // fused s-partials: sum relu'd row over this block's valid n range
    {
        int row = tid >> 1, half = tid & 1;
        int vcnt = HWn - n0; if (vcnt > 128) vcnt = 128;
        float bias = phi_b[row];
        float sum = 0.f;
        int cbeg = half * 64, cend = cbeg + 64; if (cend > vcnt) cend = vcnt;
        for (int c = cbeg; c < cend; c++) sum += fmaxf(Cs[row * 132 + c] + bias, 0.f);
        float other = __shfl_xor_sync(0xffffffffu, sum, 1);
        if (half == 0) g_spart[(b * Kw + row) * 25 + blockIdx.x] = sum + other;
    }
}

// ---------------- 5) s reduce: g_s[bk] = sum of 25 partials ----------------
__global__ void s_reduce_kernel() {
    int idx = blockIdx.x * 256 + threadIdx.x;
    if (idx < Bsz * Kw) {
        const float* p = &g_spart[idx * 25];
        float s = 0.f;
#pragma unroll
        for (int i = 0; i < 25; i++) s += p[i];
        g_s[idx] = s;
    }
}

// ---------------- 6) fused D/inv + P in two layouts ----------------
// grid (49, B): 64-n tile per block. Reads phi tile once to smem.
__global__ __launch_bounds__(256) void dps_kernel() {
    __shared__ __half ph[128][72];
    __shared__ float coef[Kw];
    __shared__ float red[4][64];
    __shared__ float invs[64];
    int n0 = blockIdx.x * 64, b = blockIdx.y;
    int tid = threadIdx.x;
    const __half* phib = g_phi + (size_t)b * Kw * HWn;

    if (tid < Kw) coef[tid] = g_rou[b * Kw + tid] * g_s[b * Kw + tid];
    // load tile: 128 rows x 64 halves = 1024 uint4
#pragma unroll
    for (int j = 0; j < 4; j++) {
        int f = tid + j * 256;
        int m = f >> 3, q = f & 7;
        *(uint4*)&ph[m][q * 8] = *(const uint4*)&phib[(size_t)m * HWn + n0 + q * 8];
    }
    __syncthreads();
    // D[n] = sum_k ph[k][n]*coef[k], split over 4 thread groups
    {
        int nl = tid & 63, kq = tid >> 6;
        float a = 0.f;
#pragma unroll 8
        for (int k = kq * 32; k < kq * 32 + 32; k++)
            a += __half2float(ph[k][nl]) * coef[k];
        red[kq][nl] = a;
    }
    __syncthreads();
    if (tid < 64)
        invs[tid] = rsqrtf(red[0][tid] + red[1][tid] + red[2][tid] + red[3][tid] + 1e-8f);
    __syncthreads();
    // write P = phi*inv, [k][n] layout
    __half* phb = g_Ph + (size_t)b * Kw * HWn;
#pragma unroll
    for (int j = 0; j < 4; j++) {
        int f = tid + j * 256;
        int m = f >> 3, q = f & 7;
        __half h[8];
#pragma unroll
        for (int e = 0; e < 8; e++) {
            int nl = q * 8 + e;
            h[e] = __float2half(__half2float(ph[m][nl]) * invs[nl]);
        }
        *(uint4*)&phb[(size_t)m * HWn + n0 + q * 8] = *(uint4*)h;
    }
    // write Pt, [n][k] layout
    __half* ptb = g_Pth + (size_t)b * HWn * Kw;
#pragma unroll
    for (int j = 0; j < 4; j++) {
        int f = tid + j * 256;
        int nl = f >> 4, kq = f & 15;
        float iv = invs[nl];
        __half h[8];
#pragma unroll
        for (int e = 0; e < 8; e++)
            h[e] = __float2half(__half2float(ph[kq * 8 + e][nl]) * iv);
        *(uint4*)&ptb[(size_t)(n0 + nl) * Kw + kq * 8] = *(uint4*)h;
    }
}

// ---------------- 7) t GEMM: FP16 wmma, K-chunk 64, 3-stage, split-K=2 (25/24) ----------------
#define T_AS 72
#define T_BS 72
#define T_AF (128 * T_AS)                   // 9216 halves
#define T_BF (64 * T_BS)                    // 4608 halves
#define T_STG (T_AF + T_BF)                 // 13824 halves = 27648 B
__global__ __launch_bounds__(256, 2) void t_gemm_h() {
    extern __shared__ char smraw[];
    __half* smh = (__half*)smraw;
    int c0 = blockIdx.x * 64, split = blockIdx.y, b = blockIdx.z;
    const __half* phb = g_Ph + (size_t)b * Kw * HWn;
    const __half* xfh = g_xh + (size_t)b * Cc * HWn;   // flat: X2[n][c]
    int tid = threadIdx.x, wid = tid >> 5;
    int wm = wid & 3, wn = wid >> 2;        // warp tile 32(k) x 32(c)
    int cstart = split ? 25 : 0;
    const int NCH = split ? 24 : 25;

    HFragC acc[2][2];
#pragma unroll
    for (int i = 0; i < 2; i++)
#pragma unroll
        for (int j = 0; j < 2; j++) wmma::fill_fragment(acc[i][j], 0.f);

    auto prefetch = [&](int ch) {
        __half* A = smh + (ch % 3) * T_STG;
        __half* B = A + T_AF;
        int nb = (cstart + ch) * 64;
#pragma unroll
        for (int j = 0; j < 4; j++) {       // A: P 128x64
            int f = tid + j * 256;
            int m = f >> 3, q = f & 7;
            cpa16(s2u(&A[m * T_AS + q * 8]), &phb[(size_t)m * HWn + nb + q * 8]);
        }
#pragma unroll
        for (int j = 0; j < 2; j++) {       // B: X2h 64x64
            int f = tid + j * 256;
            int kk = f >> 3, q = f & 7;
            cpa16(s2u(&B[kk * T_BS + q * 8]), &xfh[(size_t)(nb + kk) * Cc + c0 + q * 8]);
        }
        CP_COMMIT();
    };

    prefetch(0); prefetch(1);
    for (int ch = 0; ch < NCH; ch++) {
        if (ch < NCH - 1) CP_WAIT(1); else CP_WAIT(0);
        __syncthreads();
        if (ch + 2 < NCH) prefetch(ch + 2);
        __half* A = smh + (ch % 3) * T_STG;
        __half* B = A + T_AF;
#pragma unroll
        for (int s = 0; s < 4; s++) {
            HFragA a[2]; HFragB bf[2];
#pragma unroll
            for (int i = 0; i < 2; i++)
                wmma::load_matrix_sync(a[i], &A[(wm * 32 + i * 16) * T_AS + s * 16], T_AS);
#pragma unroll
            for (int j = 0; j < 2; j++)
                wmma::load_matrix_sync(bf[j], &B[(s * 16) * T_BS + wn * 32 + j * 16], T_BS);
#pragma unroll
            for (int i = 0; i < 2; i++)
#pragma unroll
                for (int j = 0; j < 2; j++) wmma::mma_sync(acc[i][j], a[i], bf[j], acc[i][j]);
        }
    }
    float* tb = (split ? g_t2 : g_t) + (size_t)b * Kw * Cc;
#pragma unroll
    for (int i = 0; i < 2; i++)
#pragma unroll
        for (int j = 0; j < 2; j++)
            wmma::store_matrix_sync(&tb[(size_t)(wm * 32 + i * 16) * Cc + c0 + wn * 32 + j * 16],
                                    acc[i][j], Cc, wmma::mem_row_major);
}

// ---------------- 8) w GEMM (SIMT fp32): wTh[co][k] = -rou[k]*((t0+t1)@zetaT)[k][co] ----------------
__global__ __launch_bounds__(256) void w_gemm_kernel() {
    int b = blockIdx.z, m0 = blockIdx.y * 64, c0 = blockIdx.x * 64;
    const float* tb = g_t + (size_t)b * Kw * Cc;
    const float* tb2 = g_t2 + (size_t)b * Kw * Cc;
    __shared__ float As[16][64];
    __shared__ float Bs[16][64];
    float acc[4][4] = {};
    int tid = threadIdx.x, tx = tid & 15, ty = tid >> 4;

    for (int kk0 = 0; kk0 < Cc; kk0 += 16) {
        __syncthreads();
        {
            int m = tid >> 2, q = tid & 3;
            size_t off = (size_t)(m0 + m) * Cc + kk0 + q * 4;
            float4 v = *(const float4*)&tb[off];
            float4 v2 = *(const float4*)&tb2[off];
            As[q * 4 + 0][m] = v.x + v2.x; As[q * 4 + 1][m] = v.y + v2.y;
            As[q * 4 + 2][m] = v.z + v2.z; As[q * 4 + 3][m] = v.w + v2.w;
        }
        {
            int kk = tid >> 4, c4 = tid & 15;
            float4 v = *(const float4*)&g_zetaT[(size_t)(kk0 + kk) * Cc + c0 + c4 * 4];
            *(float4*)&Bs[kk][c4 * 4] = v;
        }
        __syncthreads();
#pragma unroll
        for (int kk = 0; kk < 16; kk++) {
            float4 a = *(float4*)&As[kk][ty * 4];
            float4 bb = *(float4*)&Bs[kk][tx * 4];
            float av[4] = {a.x, a.y, a.z, a.w};
            float bv[4] = {bb.x, bb.y, bb.z, bb.w};
#pragma unroll
            for (int i = 0; i < 4; i++)
#pragma unroll
                for (int jj = 0; jj < 4; jj++) acc[i][jj] += av[i] * bv[jj];
        }
    }
    __half* wtb = g_wTh + (size_t)b * Cc * Kw;          // [co][k]
#pragma unroll
    for (int i = 0; i < 4; i++) {
        int m = m0 + ty * 4 + i;                        // k index
        float r = -g_rou[b * Kw + m];
#pragma unroll
        for (int jj = 0; jj < 4; jj++) {
            int c = c0 + tx * 4 + jj;                   // co index
            wtb[(size_t)c * Kw + m] = __float2half(r * acc[i][jj]);
        }
    }
}

// ---------------- 9) fused out GEMM: FP16 wmma, K-chunk 64, 3-stage, 1 sync/iter ----------------
// D[n=128, co=128] = [X2|Pt][n,:] @ [zeta_w ; wT][co,:]^T, K=640. grid (25, 4, B).
#define O_AS 72
#define O_AF (128 * O_AS)                   // 9216 halves
#define O_STG (2 * O_AF)                    // 18432 halves = 36864 B
__global__ __launch_bounds__(256, 2) void out_gemm_h(
    const float* __restrict__ x, const float* __restrict__ zeta_b, float* __restrict__ out) {
    extern __shared__ char smraw[];
    __half* smh = (__half*)smraw;
    float* Cs = (float*)smraw;              // [128][132] overlay
    int n0 = blockIdx.x * 128, c0 = blockIdx.y * 128, b = blockIdx.z;
    const float* xb = x + (size_t)b * Cc * HWn;
    const __half* xfh = g_xh + (size_t)b * Cc * HWn;   // flat: X2[n][c]
    const __half* pthb = g_Pth + (size_t)b * HWn * Kw;
    const __half* wthb = g_wTh + (size_t)b * Cc * Kw;
    int tid = threadIdx.x, wid = tid >> 5;
    int wm = wid & 3, wn = wid >> 2;        // warp tile 32(n) x 64(co)

    HFragC acc[2][4];
#pragma unroll
    for (int i = 0; i < 2; i++)
#pragma unroll
        for (int j = 0; j < 4; j++) wmma::fill_fragment(acc[i][j], 0.f);

    auto prefetch = [&](int ch) {
        __half* A = smh + (ch % 3) * O_STG;
        __half* B = A + O_AF;
        int k0 = ch * 64;
#pragma unroll
        for (int j = 0; j < 4; j++) {       // A: rows n, 128x64
            int f = tid + j * 256;
            int m = f >> 3, q = f & 7;
            int n = n0 + m;
            bool valid = n < HWn;
            int ns = valid ? n : (HWn - 1);
            const __half* src = (k0 < Cc)
                ? &xfh[(size_t)ns * Cc + k0 + q * 8]
                : &pthb[(size_t)ns * Kw + (k0 - Cc) + q * 8];
            cpa16z(s2u(&A[m * O_AS + q * 8]), src, valid);
        }
#pragma unroll
        for (int j = 0; j < 4; j++) {       // B: rows co, 128x64 (K-major -> col_major frags)
            int f = tid + j * 256;
            int m = f >> 3, q = f & 7;
            int co = c0 + m;
            const __half* src = (k0 < Cc)
                ? &g_zwh[(size_t)co * Cc + k0 + q * 8]
                : &wthb[(size_t)co * Kw + (k0 - Cc) + q * 8];
            cpa16(s2u(&B[m * O_AS + q * 8]), src);
        }
        CP_COMMIT();
    };

    prefetch(0); prefetch(1);
    const int NCH = 10;                     // 640 / 64; k0=512 boundary chunk-aligned
    for (int ch = 0; ch < NCH; ch++) {
        if (ch < NCH - 1) CP_WAIT(1); else CP_WAIT(0);
        __syncthreads();                    // chunk ch visible; stage (ch+2)%3 free
        if (ch + 2 < NCH) prefetch(ch + 2);
        __half* A = smh + (ch % 3) * O_STG;
        __half* B = A + O_AF;
#pragma unroll
        for (int s = 0; s < 4; s++) {
            HFragA a[2]; HFragBc bf[4];
#pragma unroll
            for (int i = 0; i < 2; i++)
                wmma::load_matrix_sync(a[i], &A[(wm * 32 + i * 16) * O_AS + s * 16], O_AS);
#pragma unroll
            for (int j = 0; j < 4; j++)
                wmma::load_matrix_sync(bf[j], &B[(wn * 64 + j * 16) * O_AS + s * 16], O_AS);
#pragma unroll
            for (int i = 0; i < 2; i++)
#pragma unroll
                for (int j = 0; j < 4; j++) wmma::mma_sync(acc[i][j], a[i], bf[j], acc[i][j]);
        }
    }
    __syncthreads();
#pragma unroll
    for (int i = 0; i < 2; i++)
#pragma unroll
        for (int j = 0; j < 4; j++)
            wmma::store_matrix_sync(&Cs[(wm * 32 + i * 16) * 132 + wn * 64 + j * 16],
                                    acc[i][j], 132, wmma::mem_row_major);
    __syncthreads();
    float* outb = out + (size_t)b * Cc * HWn;
#pragma unroll
    for (int j = 0; j < 16; j++) {
        int f = tid + j * 256;
        int m = f >> 5, c4 = f & 31;
        int n = n0 + m;
        if (n < HWn) {
            int c = c0 + c4 * 4;
            size_t idx = (size_t)n * Cc + c;
            float4 xv = *(const float4*)&xb[idx];
            float4 bz = *(const float4*)&zeta_b[c];
            const float* s = &Cs[m * 132 + c4 * 4];
            float4 v;
            v.x = xv.x + fmaxf(s[0] + bz.x, 0.f);
            v.y = xv.y + fmaxf(s[1] + bz.y, 0.f);
            v.z = xv.z + fmaxf(s[2] + bz.z, 0.f);
            v.w = xv.w + fmaxf(s[3] + bz.w, 0.f);
            *(float4*)&outb[idx] = v;
        }
    }
}

// ---------------- launch ----------------
extern "C" void kernel_launch(void* const* d_in, const int* in_sizes, int n_in,
                              void* d_out, int out_size) {
    const float* x      = (const float*)d_in[0];
    const float* y      = (const float*)d_in[1];
    const float* phi_w  = (const float*)d_in[2];
    const float* phi_b  = (const float*)d_in[3];
    const float* rou_w  = (const float*)d_in[4];
    const float* rou_b  = (const float*)d_in[5];
    const float* zeta_w = (const float*)d_in[6];
    const float* zeta_b = (const float*)d_in[7];
    float* out = (float*)d_out;

    const int PHI_SMEM = 3 * PH_STG * 2;    // 107520 B (>= Cs 67584)
    const int T_SMEM   = 3 * T_STG * 2;     // 82944 B
    const int O_SMEM   = 3 * O_STG * 2;     // 110592 B (>= Cs 67584)
    cudaFuncSetAttribute(phi_gemm_h, cudaFuncAttributeMaxDynamicSharedMemorySize, PHI_SMEM);
    cudaFuncSetAttribute(t_gemm_h,   cudaFuncAttributeMaxDynamicSharedMemorySize, T_SMEM);
    cudaFuncSetAttribute(out_gemm_h, cudaFuncAttributeMaxDynamicSharedMemorySize, O_SMEM);

    pool_kernel<<<Bsz * Cc, 256>>>(y);
    rou_kernel<<<Bsz, 128>>>(rou_w, rou_b);
    transpose_kernel<<<dim3(Cc / 32, Cc / 32), dim3(32, 8)>>>(zeta_w);
    castw_kernel<<<(Cc * Cc + 255) / 256, 256>>>(phi_w, zeta_w);
    xh_kernel<<<(int)(((size_t)Bsz * Cc * HWn / 8 + 255) / 256), 256>>>(x);
    phi_gemm_h<<<dim3(25, Bsz), 256, PHI_SMEM>>>(phi_b);
    s_reduce_kernel<<<(Bsz * Kw + 255) / 256, 256>>>();
    dps_kernel<<<dim3(49, Bsz), 256>>>();
    t_gemm_h<<<dim3(8, 2, Bsz), 256, T_SMEM>>>();
    w_gemm_kernel<<<dim3(Cc / 64, Kw / 64, Bsz), 256>>>();
    out_gemm_h<<<dim3(25, 4, Bsz), 256, O_SMEM>>>(x, zeta_b, out);
}